// round 17
// baseline (speedup 1.0000x reference)
#include <cuda_runtime.h>
#include <cuda_bf16.h>
#include <math.h>

#define BATCH 64
#define TLEN  512
#define DIM   512

#define NGRP   4
#define GBLKS  32
#define BPG    16
#define CPB    16

// -------- device scratch --------
__device__ float g_x[3][TLEN * BATCH * DIM];   // [gate][t][b][j]
__device__ float g_h[DIM * BATCH];             // [j][b]
__device__ float g_rh[DIM * BATCH];            // [j][b]
__device__ unsigned int g_cnt[NGRP * 32];      // one counter per group, 128B apart

// packed f32x2 helpers (Blackwell dual-FMA)
__device__ __forceinline__ unsigned long long pk2(float x, float y) {
    unsigned long long r;
    asm("mov.b64 %0, {%1, %2};" : "=l"(r) : "f"(x), "f"(y));
    return r;
}
__device__ __forceinline__ void fma2(unsigned long long& c, unsigned long long a,
                                     unsigned long long b) {
    asm("fma.rn.f32x2 %0, %1, %2, %0;" : "+l"(c) : "l"(a), "l"(b));
}
__device__ __forceinline__ void unpk2(unsigned long long v, float& lo, float& hi) {
    asm("mov.b64 {%0, %1}, %2;" : "=f"(lo), "=f"(hi) : "l"(v));
}

// =================================================================
// Phase 1: input projections, fp32 FFMA2 SIMT
// BM=128, BN=128, BK=16, 256 threads.
// Warp w owns m-rows [16w,16w+16) (a-loads are warp-broadcast LDS),
// lane owns 4 n-cols. Thread tile = 16m (8 f32x2 pairs) x 4n.
// =================================================================
#define PAS 132   // As[k][m] stride (16B-aligned rows: 132 = 4*33)
#define PBS 132   // Bs[k][n] stride

__global__ __launch_bounds__(256) void proj_kernel(
    const float* __restrict__ X,
    const float* __restrict__ Wz, const float* __restrict__ Wr, const float* __restrict__ Wh,
    const float* __restrict__ bz, const float* __restrict__ br, const float* __restrict__ bh)
{
    __shared__ float As[16 * PAS];   // [k][m]
    __shared__ float Bs[16 * PBS];   // [k][n]

    if (blockIdx.x == 0 && blockIdx.y == 0 && blockIdx.z == 0 && threadIdx.x < NGRP * 32)
        g_cnt[threadIdx.x] = 0u;

    const int mat = blockIdx.z;
    const float* W    = (mat == 0) ? Wz : ((mat == 1) ? Wr : Wh);
    const float* bias = (mat == 0) ? bz : ((mat == 1) ? br : bh);
    float* dst = &g_x[mat][0];

    const int m0 = blockIdx.y * 128;
    const int n0 = blockIdx.x * 128;
    const int tid  = threadIdx.x;
    const int w    = tid >> 5;        // warp id = m-slice
    const int lane = tid & 31;        // n-group (4 cols)

    unsigned long long acc[8][4];
#pragma unroll
    for (int p = 0; p < 8; ++p)
#pragma unroll
        for (int n = 0; n < 4; ++n) acc[p][n] = 0ULL;

    for (int kt = 0; kt < 512; kt += 16) {
        // stage X tile [128 m][16 k] transposed -> As[k][m]
#pragma unroll
        for (int ii = 0; ii < 2; ++ii) {
            int i = tid + ii * 256;           // 0..511 float4 index
            int r = i >> 2;                   // m row 0..127
            int cq = i & 3;                   // which float4 of the 16-k row
            float4 v = *(const float4*)&X[(m0 + r) * 512 + kt + cq * 4];
            As[(cq * 4 + 0) * PAS + r] = v.x;
            As[(cq * 4 + 1) * PAS + r] = v.y;
            As[(cq * 4 + 2) * PAS + r] = v.z;
            As[(cq * 4 + 3) * PAS + r] = v.w;
        }
        // stage W tile [16 k][128 n] -> Bs[k][n] (coalesced, conflict-free)
#pragma unroll
        for (int ii = 0; ii < 2; ++ii) {
            int idx = tid + ii * 256;         // 0..511
            int rr = idx >> 5;                // k row 0..15
            int cc = (idx & 31) * 4;          // n col
            *(float4*)&Bs[rr * PBS + cc] = *(const float4*)&W[(kt + rr) * 512 + n0 + cc];
        }
        __syncthreads();

#pragma unroll
        for (int k = 0; k < 16; ++k) {
            const float* Ar = &As[k * PAS + w * 16];
            ulonglong2 a01 = *(const ulonglong2*)(Ar + 0);
            ulonglong2 a23 = *(const ulonglong2*)(Ar + 4);
            ulonglong2 a45 = *(const ulonglong2*)(Ar + 8);
            ulonglong2 a67 = *(const ulonglong2*)(Ar + 12);
            float4 bv = *(const float4*)&Bs[k * PBS + lane * 4];
            unsigned long long u0 = pk2(bv.x, bv.x);
            unsigned long long u1 = pk2(bv.y, bv.y);
            unsigned long long u2 = pk2(bv.z, bv.z);
            unsigned long long u3 = pk2(bv.w, bv.w);
            unsigned long long ap[8] = {a01.x, a01.y, a23.x, a23.y,
                                        a45.x, a45.y, a67.x, a67.y};
#pragma unroll
            for (int p = 0; p < 8; ++p) {
                fma2(acc[p][0], ap[p], u0);
                fma2(acc[p][1], ap[p], u1);
                fma2(acc[p][2], ap[p], u2);
                fma2(acc[p][3], ap[p], u3);
            }
        }
        __syncthreads();
    }

    // epilogue: rows m0+16w+2p(+1), cols n0+4*lane; write time-major [t][b][j]
    float4 bvv = *(const float4*)&bias[n0 + lane * 4];
#pragma unroll
    for (int p = 0; p < 8; ++p) {
        float lo0, hi0, lo1, hi1, lo2, hi2, lo3, hi3;
        unpk2(acc[p][0], lo0, hi0);
        unpk2(acc[p][1], lo1, hi1);
        unpk2(acc[p][2], lo2, hi2);
        unpk2(acc[p][3], lo3, hi3);
        int m = m0 + w * 16 + 2 * p;          // m = b*512 + t
        int t0 = m & 511,       bb0 = m >> 9;
        int t1 = (m + 1) & 511, bb1 = (m + 1) >> 9;
        float4 o0 = make_float4(lo0 + bvv.x, lo1 + bvv.y, lo2 + bvv.z, lo3 + bvv.w);
        float4 o1 = make_float4(hi0 + bvv.x, hi1 + bvv.y, hi2 + bvv.z, hi3 + bvv.w);
        *(float4*)&dst[(t0 * 64 + bb0) * 512 + n0 + lane * 4] = o0;
        *(float4*)&dst[(t1 * 64 + bb1) * 512 + n0 + lane * 4] = o1;
    }
}

// =================================================================
// Phase 2: persistent GRU (R11 verbatim: FFMA2 loops, sync-first
// barrier with tid0 fence, cross-barrier prefetch rotation)
// =================================================================
#define SM_HS   (512*16)
#define SM_RHS  (512*16)
#define SM_UZR  (512*36)
#define SM_UH   (512*18)
#define RSTR    38
#define SM_RED  (16*16*RSTR)
#define SM_ZS   (16*16)
#define SMEM_FLOATS (SM_HS + SM_RHS + SM_UZR + SM_UH + SM_RED + SM_ZS + 32)

__device__ __forceinline__ void group_barrier(unsigned int* cnt, unsigned int target) {
    __syncthreads();
    if (threadIdx.x == 0) {
        __threadfence();
        atomicAdd(cnt, 1u);
        while (*((volatile unsigned int*)cnt) < target) { }
    }
    __syncthreads();
}

__global__ __launch_bounds__(256) void gru_kernel(
    const float* __restrict__ Uz, const float* __restrict__ Ur, const float* __restrict__ Uh,
    const int* __restrict__ mask, float* __restrict__ out)
{
    extern __shared__ float sm[];
    float* h_s   = sm;
    float* rh_s  = h_s + SM_HS;
    float* Uzr_s = rh_s + SM_RHS;
    float* Uh_s  = Uzr_s + SM_UZR;
    float* red   = Uh_s + SM_UH;
    float* z_s   = red + SM_RED;

    const int tid = threadIdx.x;
    const int bx  = blockIdx.x;
    const int bg  = bx >> 5;
    const int jg  = bx & 31;
    const int jb  = jg * CPB;
    const int b_base = bg * BPG;
    unsigned int* cnt = &g_cnt[bg * 32];

    for (int i = tid; i < 512 * 16; i += 256) {
        int k = i >> 4, c = i & 15;
        Uzr_s[k * 36 + c]      = Uz[k * 512 + jb + c];
        Uzr_s[k * 36 + 16 + c] = Ur[k * 512 + jb + c];
        Uh_s [k * 18 + c]      = Uh[k * 512 + jb + c];
    }

    g_h[bx * 256 + tid] = 0.f;

    unsigned int round = 0;
    group_barrier(cnt, ++round * GBLKS);

    const int chunk = tid >> 4;
    const int sub   = tid & 15;
    const int b0    = (sub >> 3) * 8;
    const int c0A   = (sub & 7) * 4;
    const int c0B   = (sub & 7) * 2;

    const int bl0  = tid & 15;
    const int cz   = tid >> 4;
    const int btE  = bl0 >> 3;
    const int bhat = bl0 & 7;

    const float* xzp = &g_x[0][(b_base + bl0) * 512 + jb + cz];
    const float* xrp = &g_x[1][(b_base + bl0) * 512 + jb + cz];
    const float* xhp = &g_x[2][(b_base + bl0) * 512 + jb + cz];
    const int*   mp  = &mask[(b_base + bl0) * 512];

    // prologue prefetch for t = 0
    float xz = xzp[0];
    float xr = xrp[0];

    for (int t = 0; t < TLEN; ++t) {
        // =================== Phase A: z and r ===================
        float xh   = xhp[t * 32768];
        int   mreg = mp[t];

#pragma unroll 2
        for (int i = tid; i < 2048; i += 256) {
            int j = i >> 2, bq = (i & 3) << 2;
            float4 v = __ldcg((const float4*)(g_h + j * 64 + b_base + bq));
            *(float4*)&h_s[j * 16 + bq] = v;
        }
        __syncthreads();

        unsigned long long accp[4][4];
#pragma unroll
        for (int p = 0; p < 4; ++p)
#pragma unroll
            for (int c = 0; c < 4; ++c) accp[p][c] = 0ULL;

#pragma unroll 4
        for (int s = 0; s < 32; ++s) {
            int k = chunk + (s << 4);
            ulonglong2 ha = *(const ulonglong2*)(h_s + k * 16 + b0);
            ulonglong2 hb = *(const ulonglong2*)(h_s + k * 16 + b0 + 4);
            float4 uv = *(const float4*)&Uzr_s[k * 36 + c0A];
            unsigned long long u0 = pk2(uv.x, uv.x);
            unsigned long long u1 = pk2(uv.y, uv.y);
            unsigned long long u2 = pk2(uv.z, uv.z);
            unsigned long long u3 = pk2(uv.w, uv.w);
            unsigned long long hp[4] = {ha.x, ha.y, hb.x, hb.y};
#pragma unroll
            for (int p = 0; p < 4; ++p) {
                fma2(accp[p][0], hp[p], u0);
                fma2(accp[p][1], hp[p], u1);
                fma2(accp[p][2], hp[p], u2);
                fma2(accp[p][3], hp[p], u3);
            }
        }

        {
            int slot = (chunk * 16 + sub) * RSTR;
#pragma unroll
            for (int p = 0; p < 4; ++p)
#pragma unroll
                for (int c = 0; c < 4; ++c)
                    *(unsigned long long*)&red[slot + c * 8 + 2 * p] = accp[p][c];
        }
        __syncthreads();

        {
            float s0 = 0.f, s1 = 0.f;
#pragma unroll
            for (int c = 0; c < 16; ++c) {
                s0 += red[(c * 16 + btE * 8 + (cz >> 2)) * RSTR + (cz & 3) * 8 + bhat];
                s1 += red[(c * 16 + btE * 8 + 4 + (cz >> 2)) * RSTR + (cz & 3) * 8 + bhat];
            }
            float zg = 1.f / (1.f + __expf(-(xz + s0)));
            z_s[cz * 16 + bl0] = zg;
            int jglob = jb + cz;
            float rg = 1.f / (1.f + __expf(-(xr + s1)));
            g_rh[jglob * 64 + b_base + bl0] = rg * h_s[jglob * 16 + bl0];
        }
        group_barrier(cnt, ++round * GBLKS);

        // =================== Phase B: candidate + update ===================
        if (t + 1 < TLEN) {
            xz = xzp[(t + 1) * 32768];
            xr = xrp[(t + 1) * 32768];
        }

#pragma unroll 2
        for (int i = tid; i < 2048; i += 256) {
            int j = i >> 2, bq = (i & 3) << 2;
            float4 v = __ldcg((const float4*)(g_rh + j * 64 + b_base + bq));
            *(float4*)&rh_s[j * 16 + bq] = v;
        }
        __syncthreads();

        unsigned long long acc2p[4][2];
#pragma unroll
        for (int p = 0; p < 4; ++p) { acc2p[p][0] = 0ULL; acc2p[p][1] = 0ULL; }

#pragma unroll 4
        for (int s = 0; s < 32; ++s) {
            int k = chunk + (s << 4);
            ulonglong2 ra = *(const ulonglong2*)(rh_s + k * 16 + b0);
            ulonglong2 rb = *(const ulonglong2*)(rh_s + k * 16 + b0 + 4);
            float2 uv = *(const float2*)&Uh_s[k * 18 + c0B];
            unsigned long long u0 = pk2(uv.x, uv.x);
            unsigned long long u1 = pk2(uv.y, uv.y);
            unsigned long long rp[4] = {ra.x, ra.y, rb.x, rb.y};
#pragma unroll
            for (int p = 0; p < 4; ++p) {
                fma2(acc2p[p][0], rp[p], u0);
                fma2(acc2p[p][1], rp[p], u1);
            }
        }

        {
            int slot = (chunk * 16 + sub) * RSTR;
#pragma unroll
            for (int p = 0; p < 4; ++p) {
                *(unsigned long long*)&red[slot + 0 * 8 + 2 * p] = acc2p[p][0];
                *(unsigned long long*)&red[slot + 1 * 8 + 2 * p] = acc2p[p][1];
            }
        }
        __syncthreads();

        {
            float s2 = 0.f;
#pragma unroll
            for (int c = 0; c < 16; ++c)
                s2 += red[(c * 16 + btE * 8 + (cz >> 1)) * RSTR + (cz & 1) * 8 + bhat];
            float hh = tanhf(xh + s2);
            float zg = z_s[cz * 16 + bl0];
            int jglob = jb + cz;
            float hold = h_s[jglob * 16 + bl0];
            float hn   = zg * hold + (1.f - zg) * hh;
            float res  = (mreg > 0) ? hn : hold;
            g_h[jglob * 64 + b_base + bl0] = res;
            if (t == TLEN - 1) out[(b_base + bl0) * 512 + jglob] = res;
        }
        group_barrier(cnt, ++round * GBLKS);
    }
}

// =================================================================
extern "C" void kernel_launch(void* const* d_in, const int* in_sizes, int n_in,
                              void* d_out, int out_size) {
    (void)in_sizes; (void)n_in; (void)out_size;
    const float* X    = (const float*)d_in[0];
    const int*   mask = (const int*)  d_in[1];
    const float* Wz   = (const float*)d_in[2];
    const float* Uz   = (const float*)d_in[3];
    const float* bz   = (const float*)d_in[4];
    const float* Wr   = (const float*)d_in[5];
    const float* Ur   = (const float*)d_in[6];
    const float* br   = (const float*)d_in[7];
    const float* Wh   = (const float*)d_in[8];
    const float* Uh   = (const float*)d_in[9];
    const float* bh   = (const float*)d_in[10];
    float* out = (float*)d_out;

    const int smem_bytes = SMEM_FLOATS * (int)sizeof(float);
    cudaFuncSetAttribute(gru_kernel, cudaFuncAttributeMaxDynamicSharedMemorySize, smem_bytes);

    proj_kernel<<<dim3(4, 256, 3), 256>>>(X, Wz, Wr, Wh, bz, br, bh);
    gru_kernel<<<128, 256, smem_bytes>>>(Uz, Ur, Uh, mask, out);
}